// round 1
// baseline (speedup 1.0000x reference)
#include <cuda_runtime.h>
#include <math.h>
#include <stdint.h>

// Problem constants
#define T_TOKENS 4096      // B*S
#define HDIM     1280
#define EXPERTS  63        // routed experts
#define IDIM     1280
#define TOPK     7
#define CAP      4096      // max tokens per expert
#define ASSIGN   (T_TOKENS*TOPK)   // 28672 routed assignment rows

// GEMM tiling
#define BM 128
#define BN 64
#define BK 16
#define ASTRIDE (BK+4)   // 20 floats  -> conflict-free A-frag LDS
#define BSTRIDE (BN+8)   // 72 floats  -> conflict-free B-frag LDS

// ---------------- scratch (static device memory; no allocation) -------------
__device__ float g_h_routed[(size_t)ASSIGN  * IDIM];   // gelu(x@w1+b1), packed rows
__device__ float g_h_shared[(size_t)T_TOKENS * IDIM];
__device__ float g_o_routed[(size_t)ASSIGN  * HDIM];   // h@w2+b2 (ungated)
__device__ float g_o_shared[(size_t)T_TOKENS * HDIM];
__device__ int   g_cnt[64];
__device__ int   g_off[64];
__device__ int   g_tok[EXPERTS * CAP];                 // token id per (expert, slot)
__device__ int   g_eidx[T_TOKENS * TOPK];
__device__ int   g_epos[T_TOKENS * TOPK];
__device__ float g_gate[T_TOKENS * TOPK];

// ---------------------------------------------------------------------------
__global__ void zero_kernel() {
    if (threadIdx.x < 64) g_cnt[threadIdx.x] = 0;
}

// One block per token: logits -> softmax -> top-7 -> bucket by expert.
__global__ void router_kernel(const float* __restrict__ x,
                              const float* __restrict__ rw,
                              const float* __restrict__ rb) {
    __shared__ float xs[HDIM];
    __shared__ float lg[EXPERTS];
    int t = blockIdx.x;
    const float* xr = x + (size_t)t * HDIM;
    for (int i = threadIdx.x; i < HDIM; i += blockDim.x) xs[i] = xr[i];
    __syncthreads();
    int e = threadIdx.x;
    if (e < EXPERTS) {
        float acc = rb[e];
        #pragma unroll 4
        for (int h = 0; h < HDIM; h++) acc = fmaf(xs[h], rw[h * EXPERTS + e], acc);
        lg[e] = acc;
    }
    __syncthreads();
    if (threadIdx.x == 0) {
        float mx = lg[0];
        for (int i = 1; i < EXPERTS; i++) mx = fmaxf(mx, lg[i]);
        float den = 0.f;
        for (int i = 0; i < EXPERTS; i++) den += expf(lg[i] - mx);
        float inv = 1.f / den;
        for (int k = 0; k < TOPK; k++) {
            int bi = 0; float bv = lg[0];
            for (int i = 1; i < EXPERTS; i++)
                if (lg[i] > bv) { bv = lg[i]; bi = i; }   // strict > keeps lowest idx on tie
            float val = expf(bv - mx) * inv;
            int pos = atomicAdd(&g_cnt[bi], 1);
            g_tok[bi * CAP + pos] = t;
            g_eidx[t * TOPK + k] = bi;
            g_epos[t * TOPK + k] = pos;
            g_gate[t * TOPK + k] = val;
            lg[bi] = -INFINITY;
        }
    }
}

__global__ void offsets_kernel() {
    if (threadIdx.x == 0) {
        int o = 0;
        for (int e = 0; e < EXPERTS; e++) { g_off[e] = o; o += g_cnt[e]; }
    }
}

// m16n8k8 tf32 mma (fp32 bit-patterns fed directly; HW uses tf32 mantissa)
__device__ __forceinline__ void mma_tf32(float* d, const float* a, float b0, float b1) {
    asm volatile(
        "mma.sync.aligned.m16n8k8.row.col.f32.tf32.tf32.f32 "
        "{%0,%1,%2,%3}, {%4,%5,%6,%7}, {%8,%9}, {%0,%1,%2,%3};\n"
        : "+f"(d[0]), "+f"(d[1]), "+f"(d[2]), "+f"(d[3])
        : "r"(__float_as_uint(a[0])), "r"(__float_as_uint(a[1])),
          "r"(__float_as_uint(a[2])), "r"(__float_as_uint(a[3])),
          "r"(__float_as_uint(b0)),   "r"(__float_as_uint(b1)));
}

__device__ __forceinline__ float gelu_exact(float v) {
    return 0.5f * v * (1.0f + erff(v * 0.70710678118654752f));
}

// MODE 0: h = gelu(x_gathered @ w1 + b1)      (K = HDIM, N = IDIM)
// MODE 1: o = h @ w2 + b2                      (K = IDIM, N = HDIM)
// blockIdx.z == EXPERTS selects the shared expert (all 4096 tokens, identity map)
template <int MODE>
__global__ void __launch_bounds__(256) gemm_kernel(
    const float* __restrict__ x,
    const float* __restrict__ w1,  const float* __restrict__ b1,
    const float* __restrict__ w1s, const float* __restrict__ b1s,
    const float* __restrict__ w2,  const float* __restrict__ b2,
    const float* __restrict__ w2s, const float* __restrict__ b2s)
{
    const int e  = blockIdx.z;
    const int m0 = blockIdx.y * BM;
    const int n0 = blockIdx.x * BN;
    const bool se = (e == EXPERTS);
    const int cnt = se ? T_TOKENS : g_cnt[e];
    if (m0 >= cnt) return;

    __shared__ float As[BM * ASTRIDE];
    __shared__ float Bs[BK * BSTRIDE];
    __shared__ const float* Arow[BM];

    const float* Bp; const float* bias;
    if (MODE == 0) {
        Bp = se ? w1s : (w1 + (size_t)e * HDIM * IDIM);
        bias = se ? b1s : (b1 + (size_t)e * IDIM);
    } else {
        Bp = se ? w2s : (w2 + (size_t)e * IDIM * HDIM);
        bias = se ? b2s : (b2 + (size_t)e * HDIM);
    }
    const int off_e = se ? 0 : g_off[e];

    // Per-row A source pointers (gather handled once, here)
    for (int r = threadIdx.x; r < BM; r += 256) {
        int rr = m0 + r; if (rr > cnt - 1) rr = cnt - 1;  // clamp; writes guarded later
        const float* p;
        if (MODE == 0)
            p = se ? (x + (size_t)rr * HDIM)
                   : (x + (size_t)g_tok[e * CAP + rr] * HDIM);
        else
            p = se ? (g_h_shared + (size_t)rr * IDIM)
                   : (g_h_routed + (size_t)(off_e + rr) * IDIM);
        Arow[r] = p;
    }
    __syncthreads();

    const int tid  = threadIdx.x;
    const int lane = tid & 31, wid = tid >> 5;
    const int wm = wid & 3, wn = wid >> 2;       // 4 x 2 warp grid (32x32 per warp)
    const int gr = lane >> 2, tg = lane & 3;

    const int ar0 = tid >> 2;        // rows 0..63 (+64)
    const int akq = tid & 3;
    const float* ap0 = Arow[ar0];
    const float* ap1 = Arow[ar0 + 64];
    const int brow = tid >> 4;       // 0..15
    const int bkq  = tid & 15;

    float acc[2][4][4];
    #pragma unroll
    for (int a = 0; a < 2; a++)
        #pragma unroll
        for (int b = 0; b < 4; b++)
            #pragma unroll
            for (int c = 0; c < 4; c++) acc[a][b][c] = 0.f;

    for (int k0 = 0; k0 < 1280; k0 += BK) {
        float4 av0 = *(const float4*)(ap0 + k0 + 4 * akq);
        float4 av1 = *(const float4*)(ap1 + k0 + 4 * akq);
        float4 bv  = *(const float4*)(Bp + (size_t)(k0 + brow) * 1280 + n0 + 4 * bkq);
        __syncthreads();
        *(float4*)(&As[ar0 * ASTRIDE + 4 * akq])        = av0;
        *(float4*)(&As[(ar0 + 64) * ASTRIDE + 4 * akq]) = av1;
        *(float4*)(&Bs[brow * BSTRIDE + 4 * bkq])       = bv;
        __syncthreads();

        #pragma unroll
        for (int ks = 0; ks < BK; ks += 8) {
            float a[2][4];
            #pragma unroll
            for (int mf = 0; mf < 2; mf++) {
                int rb = wm * 32 + mf * 16;
                a[mf][0] = As[(rb + gr)     * ASTRIDE + ks + tg];
                a[mf][1] = As[(rb + gr + 8) * ASTRIDE + ks + tg];
                a[mf][2] = As[(rb + gr)     * ASTRIDE + ks + tg + 4];
                a[mf][3] = As[(rb + gr + 8) * ASTRIDE + ks + tg + 4];
            }
            #pragma unroll
            for (int nf = 0; nf < 4; nf++) {
                float b0 = Bs[(ks + tg)     * BSTRIDE + wn * 32 + nf * 8 + gr];
                float b1v = Bs[(ks + tg + 4) * BSTRIDE + wn * 32 + nf * 8 + gr];
                #pragma unroll
                for (int mf = 0; mf < 2; mf++)
                    mma_tf32(acc[mf][nf], a[mf], b0, b1v);
            }
        }
    }

    // Epilogue: bias (+gelu for MODE 0), write packed scratch rows
    float* obase;
    if (MODE == 0) obase = se ? g_h_shared : g_h_routed;
    else           obase = se ? g_o_shared : g_o_routed;

    #pragma unroll
    for (int mf = 0; mf < 2; mf++) {
        int rb = wm * 32 + mf * 16 + gr;
        #pragma unroll
        for (int half = 0; half < 2; half++) {
            int r = rb + half * 8;
            if (m0 + r >= cnt) continue;
            size_t orow = (size_t)(off_e + m0 + r) * 1280;  // off_e==0 for shared
            float* op = obase + orow;
            #pragma unroll
            for (int nf = 0; nf < 4; nf++) {
                int c0 = wn * 32 + nf * 8 + 2 * tg;
                float v0 = acc[mf][nf][half * 2 + 0] + bias[n0 + c0];
                float v1 = acc[mf][nf][half * 2 + 1] + bias[n0 + c0 + 1];
                if (MODE == 0) { v0 = gelu_exact(v0); v1 = gelu_exact(v1); }
                op[n0 + c0]     = v0;
                op[n0 + c0 + 1] = v1;
            }
        }
    }
}

// out[t] = x[t] + shared_ffn[t] + sum_k gate * routed_row(slot(t,k))
// Fixed k-order summation => deterministic.
__global__ void reduce_kernel(const float* __restrict__ x, float* __restrict__ out) {
    int t = blockIdx.x;
    size_t col = 4 * (size_t)threadIdx.x;
    float4 acc = *(const float4*)(x + (size_t)t * HDIM + col);
    float4 sh  = *(const float4*)(g_o_shared + (size_t)t * HDIM + col);
    acc.x += sh.x; acc.y += sh.y; acc.z += sh.z; acc.w += sh.w;
    #pragma unroll
    for (int k = 0; k < TOPK; k++) {
        int e   = g_eidx[t * TOPK + k];
        int p   = g_epos[t * TOPK + k];
        float g = g_gate[t * TOPK + k];
        const float4 v = *(const float4*)(g_o_routed + (size_t)(g_off[e] + p) * HDIM + col);
        acc.x += g * v.x; acc.y += g * v.y; acc.z += g * v.z; acc.w += g * v.w;
    }
    *(float4*)(out + (size_t)t * HDIM + col) = acc;
}

// ---------------------------------------------------------------------------
extern "C" void kernel_launch(void* const* d_in, const int* in_sizes, int n_in,
                              void* d_out, int out_size) {
    const float* x   = (const float*)d_in[0];
    const float* w1s = (const float*)d_in[1];
    const float* b1s = (const float*)d_in[2];
    const float* w2s = (const float*)d_in[3];
    const float* b2s = (const float*)d_in[4];
    const float* rw  = (const float*)d_in[5];
    const float* rb  = (const float*)d_in[6];
    const float* w1  = (const float*)d_in[7];
    const float* b1  = (const float*)d_in[8];
    const float* w2  = (const float*)d_in[9];
    const float* b2  = (const float*)d_in[10];
    float* out = (float*)d_out;

    zero_kernel<<<1, 64>>>();
    router_kernel<<<T_TOKENS, 64>>>(x, rw, rb);
    offsets_kernel<<<1, 32>>>();

    dim3 g(IDIM / BN, T_TOKENS / BM, EXPERTS + 1);   // (20, 32, 64)
    gemm_kernel<0><<<g, 256>>>(x, w1, b1, w1s, b1s, w2, b2, w2s, b2s);
    gemm_kernel<1><<<g, 256>>>(x, w1, b1, w1s, b1s, w2, b2, w2s, b2s);

    reduce_kernel<<<T_TOKENS, 320>>>(x, out);
}

// round 7
// speedup vs baseline: 1.3019x; 1.3019x over previous
#include <cuda_runtime.h>
#include <math.h>
#include <stdint.h>

// ---------------- problem constants ----------------
#define T_TOKENS 4096
#define HDIM     1280
#define EXPERTS  63
#define IDIM     1280
#define TOPK     7
#define CAP      4096
#define ASSIGN   (T_TOKENS*TOPK)

// ---------------- GEMM tiling ----------------
#define BM 128
#define BN 128
#define BK 16
#define NSTAGE 3
#define ASTRIDE 20                         // 16+4 floats, conflict-light
#define BSTRIDE 136                        // 128+8 floats, conflict-free frag LDS
#define A_FLOATS (BM*ASTRIDE)              // 2560
#define B_FLOATS (BK*BSTRIDE)              // 2176
#define STAGE_BYTES ((A_FLOATS + B_FLOATS)*4)   // 18944
#define B_OFF (A_FLOATS*4)
#define AR_BYTES 1024                      // 128 row pointers (8B each)
#define SMEM_TOTAL (AR_BYTES + NSTAGE*STAGE_BYTES)  // 57856

// ---------------- scratch (static device memory) ----------------
__device__ float g_h_routed[(size_t)ASSIGN  * IDIM];
__device__ float g_h_shared[(size_t)T_TOKENS * IDIM];
__device__ float g_o_routed[(size_t)ASSIGN  * HDIM];
__device__ float g_o_shared[(size_t)T_TOKENS * HDIM];
__device__ int   g_cnt[64];
__device__ int   g_off[64];
__device__ int   g_tok[EXPERTS * CAP];
__device__ int   g_eidx[T_TOKENS * TOPK];
__device__ int   g_epos[T_TOKENS * TOPK];
__device__ float g_gate[T_TOKENS * TOPK];

// ---------------- helpers ----------------
__device__ __forceinline__ uint32_t smem_u32(const void* p) {
    uint32_t a;
    asm("{ .reg .u64 t; cvta.to.shared.u64 t, %1; cvt.u32.u64 %0, t; }" : "=r"(a) : "l"(p));
    return a;
}
__device__ __forceinline__ void cp16(uint32_t dst, const void* src) {
    asm volatile("cp.async.cg.shared.global [%0], [%1], 16;" :: "r"(dst), "l"(src));
}
__device__ __forceinline__ void cp_commit() { asm volatile("cp.async.commit_group;" ::: "memory"); }
__device__ __forceinline__ void cp_wait1()  { asm volatile("cp.async.wait_group 1;" ::: "memory"); }

__device__ __forceinline__ void mma_tf32(float* d, const float* a, float b0, float b1) {
    asm volatile(
        "mma.sync.aligned.m16n8k8.row.col.f32.tf32.tf32.f32 "
        "{%0,%1,%2,%3}, {%4,%5,%6,%7}, {%8,%9}, {%0,%1,%2,%3};\n"
        : "+f"(d[0]), "+f"(d[1]), "+f"(d[2]), "+f"(d[3])
        : "r"(__float_as_uint(a[0])), "r"(__float_as_uint(a[1])),
          "r"(__float_as_uint(a[2])), "r"(__float_as_uint(a[3])),
          "r"(__float_as_uint(b0)),   "r"(__float_as_uint(b1)));
}

__device__ __forceinline__ float gelu_exact(float v) {
    return 0.5f * v * (1.0f + erff(v * 0.70710678118654752f));
}

// ---------------- router / bookkeeping (proven in R1) ----------------
__global__ void zero_kernel() { if (threadIdx.x < 64) g_cnt[threadIdx.x] = 0; }

__global__ void router_kernel(const float* __restrict__ x,
                              const float* __restrict__ rw,
                              const float* __restrict__ rb) {
    __shared__ float xs[HDIM];
    __shared__ float lg[EXPERTS];
    int t = blockIdx.x;
    const float* xr = x + (size_t)t * HDIM;
    for (int i = threadIdx.x; i < HDIM; i += blockDim.x) xs[i] = xr[i];
    __syncthreads();
    int e = threadIdx.x;
    if (e < EXPERTS) {
        float acc = rb[e];
        #pragma unroll 4
        for (int h = 0; h < HDIM; h++) acc = fmaf(xs[h], rw[h * EXPERTS + e], acc);
        lg[e] = acc;
    }
    __syncthreads();
    if (threadIdx.x == 0) {
        float mx = lg[0];
        for (int i = 1; i < EXPERTS; i++) mx = fmaxf(mx, lg[i]);
        float den = 0.f;
        for (int i = 0; i < EXPERTS; i++) den += expf(lg[i] - mx);
        float inv = 1.f / den;
        for (int k = 0; k < TOPK; k++) {
            int bi = 0; float bv = lg[0];
            for (int i = 1; i < EXPERTS; i++)
                if (lg[i] > bv) { bv = lg[i]; bi = i; }
            float val = expf(bv - mx) * inv;
            int pos = atomicAdd(&g_cnt[bi], 1);
            g_tok[bi * CAP + pos] = t;
            g_eidx[t * TOPK + k] = bi;
            g_epos[t * TOPK + k] = pos;
            g_gate[t * TOPK + k] = val;
            lg[bi] = -INFINITY;
        }
    }
}

__global__ void offsets_kernel() {
    if (threadIdx.x == 0) {
        int o = 0;
        for (int e = 0; e < EXPERTS; e++) { g_off[e] = o; o += g_cnt[e]; }
    }
}

// ---------------- pipelined mma.sync grouped GEMM ----------------
// 256 threads = 8 warps as 4(m) x 2(n); warp tile 32x64; CTA tile 128x128.
// MODE 0: h = gelu(gather(x) @ w1 + b1); MODE 1: o = h @ w2 + b2.
// blockIdx.z == EXPERTS -> shared expert (all tokens, identity gather).
template <int MODE>
__global__ void __launch_bounds__(256, 2) gemm_kernel(
    const float* __restrict__ x,
    const float* __restrict__ w1,  const float* __restrict__ b1,
    const float* __restrict__ w1s, const float* __restrict__ b1s,
    const float* __restrict__ w2,  const float* __restrict__ b2,
    const float* __restrict__ w2s, const float* __restrict__ b2s)
{
    const int  e   = blockIdx.z;
    const bool se  = (e == EXPERTS);
    const int  cnt = se ? T_TOKENS : g_cnt[e];
    const int  m0  = blockIdx.y * BM;
    if (m0 >= cnt) return;
    const int  n0  = blockIdx.x * BN;

    extern __shared__ char smem[];
    const float** Arow = (const float**)smem;
    const uint32_t sb = smem_u32(smem);
    const int tid = threadIdx.x;

    const float* Bp; const float* bias;
    if (MODE == 0) { Bp = se ? w1s : (w1 + (size_t)e * HDIM * IDIM); bias = se ? b1s : (b1 + (size_t)e * IDIM); }
    else           { Bp = se ? w2s : (w2 + (size_t)e * IDIM * HDIM); bias = se ? b2s : (b2 + (size_t)e * HDIM); }
    const int off_e = se ? 0 : g_off[e];

    // per-row gathered A pointers (once)
    for (int r = tid; r < BM; r += 256) {
        int rr = m0 + r; if (rr > cnt - 1) rr = cnt - 1;
        const float* p;
        if (MODE == 0) p = se ? (x + (size_t)rr * HDIM) : (x + (size_t)g_tok[e * CAP + rr] * HDIM);
        else           p = se ? (g_h_shared + (size_t)rr * IDIM) : (g_h_routed + (size_t)(off_e + rr) * IDIM);
        Arow[r] = p;
    }
    __syncthreads();

    // cp.async chunk loader: A 2 quads/thread, B 2 quads/thread
    const int a_row0 = tid >> 2,  a_c0 = tid & 3;         // quads 0..255
    const int b_row0 = tid >> 5,  b_c0 = tid & 31;        // quads 0..255
    auto load_chunk = [&](int c) {
        const uint32_t stg = sb + AR_BYTES + (uint32_t)(c % NSTAGE) * STAGE_BYTES;
        #pragma unroll
        for (int i = 0; i < 2; i++) {
            int row = a_row0 + i * 64;                    // +256 quads = +64 rows
            cp16(stg + (uint32_t)(row * ASTRIDE + a_c0 * 4) * 4,
                 Arow[row] + c * BK + a_c0 * 4);
        }
        #pragma unroll
        for (int i = 0; i < 2; i++) {
            int row = b_row0 + i * 8;                     // +256 quads = +8 rows
            cp16(stg + B_OFF + (uint32_t)(row * BSTRIDE + b_c0 * 4) * 4,
                 Bp + (size_t)(c * BK + row) * 1280 + n0 + b_c0 * 4);
        }
    };

    const int lane = tid & 31, wid = tid >> 5;
    const int wm = wid & 3, wn = wid >> 2;                // warp M=32, N=64
    const int gr = lane >> 2, tg = lane & 3;

    float acc[2][8][4];
    #pragma unroll
    for (int a = 0; a < 2; a++)
        #pragma unroll
        for (int b = 0; b < 8; b++)
            #pragma unroll
            for (int c = 0; c < 4; c++) acc[a][b][c] = 0.f;

    load_chunk(0); cp_commit();
    load_chunk(1); cp_commit();

    const int NCH = 1280 / BK;   // 80
    for (int c = 0; c < NCH; c++) {
        cp_wait1();
        __syncthreads();
        if (c + 2 < NCH) load_chunk(c + 2);
        cp_commit();

        const float* As_ = (const float*)(smem + AR_BYTES + (c % NSTAGE) * STAGE_BYTES);
        const float* Bs_ = (const float*)((const char*)As_ + B_OFF);

        #pragma unroll
        for (int ks = 0; ks < BK; ks += 8) {
            float a[2][4];
            #pragma unroll
            for (int mf = 0; mf < 2; mf++) {
                int rb = wm * 32 + mf * 16;
                a[mf][0] = As_[(rb + gr)     * ASTRIDE + ks + tg];
                a[mf][1] = As_[(rb + gr + 8) * ASTRIDE + ks + tg];
                a[mf][2] = As_[(rb + gr)     * ASTRIDE + ks + tg + 4];
                a[mf][3] = As_[(rb + gr + 8) * ASTRIDE + ks + tg + 4];
            }
            #pragma unroll
            for (int nf = 0; nf < 8; nf++) {
                int col = wn * 64 + nf * 8 + gr;
                float b0 = Bs_[(ks + tg)     * BSTRIDE + col];
                float b1 = Bs_[(ks + tg + 4) * BSTRIDE + col];
                mma_tf32(acc[0][nf], a[0], b0, b1);
                mma_tf32(acc[1][nf], a[1], b0, b1);
            }
        }
    }

    // epilogue: bias (+gelu for MODE 0) -> packed scratch
    float* obase;
    if (MODE == 0) obase = se ? g_h_shared : g_h_routed;
    else           obase = se ? g_o_shared : g_o_routed;

    #pragma unroll
    for (int mf = 0; mf < 2; mf++) {
        int rb = wm * 32 + mf * 16 + gr;
        #pragma unroll
        for (int half = 0; half < 2; half++) {
            int r = rb + half * 8;
            if (m0 + r >= cnt) continue;
            float* op = obase + (size_t)(off_e + m0 + r) * 1280;
            #pragma unroll
            for (int nf = 0; nf < 8; nf++) {
                int c0 = wn * 64 + nf * 8 + 2 * tg;
                float v0 = acc[mf][nf][half * 2 + 0] + bias[n0 + c0];
                float v1 = acc[mf][nf][half * 2 + 1] + bias[n0 + c0 + 1];
                if (MODE == 0) { v0 = gelu_exact(v0); v1 = gelu_exact(v1); }
                op[n0 + c0]     = v0;
                op[n0 + c0 + 1] = v1;
            }
        }
    }
}

// ---------------- final gather-reduce ----------------
__global__ void reduce_kernel(const float* __restrict__ x, float* __restrict__ out) {
    int t = blockIdx.x;
    size_t col = 4 * (size_t)threadIdx.x;
    float4 acc = *(const float4*)(x + (size_t)t * HDIM + col);
    float4 sh  = *(const float4*)(g_o_shared + (size_t)t * HDIM + col);
    acc.x += sh.x; acc.y += sh.y; acc.z += sh.z; acc.w += sh.w;
    #pragma unroll
    for (int k = 0; k < TOPK; k++) {
        int e   = g_eidx[t * TOPK + k];
        int p   = g_epos[t * TOPK + k];
        float g = g_gate[t * TOPK + k];
        const float4 v = *(const float4*)(g_o_routed + (size_t)(g_off[e] + p) * HDIM + col);
        acc.x += g * v.x; acc.y += g * v.y; acc.z += g * v.z; acc.w += g * v.w;
    }
    *(float4*)(out + (size_t)t * HDIM + col) = acc;
}

// ---------------------------------------------------------------------------
extern "C" void kernel_launch(void* const* d_in, const int* in_sizes, int n_in,
                              void* d_out, int out_size) {
    const float* x   = (const float*)d_in[0];
    const float* w1s = (const float*)d_in[1];
    const float* b1s = (const float*)d_in[2];
    const float* w2s = (const float*)d_in[3];
    const float* b2s = (const float*)d_in[4];
    const float* rw  = (const float*)d_in[5];
    const float* rb  = (const float*)d_in[6];
    const float* w1  = (const float*)d_in[7];
    const float* b1  = (const float*)d_in[8];
    const float* w2  = (const float*)d_in[9];
    const float* b2  = (const float*)d_in[10];
    float* out = (float*)d_out;

    cudaFuncSetAttribute(gemm_kernel<0>, cudaFuncAttributeMaxDynamicSharedMemorySize, SMEM_TOTAL);
    cudaFuncSetAttribute(gemm_kernel<1>, cudaFuncAttributeMaxDynamicSharedMemorySize, SMEM_TOTAL);

    zero_kernel<<<1, 64>>>();
    router_kernel<<<T_TOKENS, 64>>>(x, rw, rb);
    offsets_kernel<<<1, 32>>>();

    dim3 g(IDIM / BN, T_TOKENS / BM, EXPERTS + 1);   // (10, 32, 64)
    gemm_kernel<0><<<g, 256, SMEM_TOTAL>>>(x, w1, b1, w1s, b1s, w2, b2, w2s, b2s);
    gemm_kernel<1><<<g, 256, SMEM_TOTAL>>>(x, w1, b1, w1s, b1s, w2, b2, w2s, b2s);

    reduce_kernel<<<T_TOKENS, 320>>>(x, out);
}